// round 13
// baseline (speedup 1.0000x reference)
#include <cuda_runtime.h>
#include <cstdint>

// y[t,b,f] = sum_{k=0..20} x[t+k,b,f] * w[f,k], zero-padded past t=T-1.
// Thread owns two adjacent features (one float2 column) and a 64-long time
// strip: 8 fully-unrolled chunks of 8 with a 20-element carried register
// window. Loads go through a per-thread cp.async (LDGSTS) staging ring in
// shared memory: registerless, scoreboardless, deep — DRAM latency is hidden
// by async depth instead of warps/registers. Producer == consumer thread, so
// no block barriers; ordering is per-thread cp.async.wait_group. Packed
// fma.rn.f32x2 halves fp32 work; streaming stores protect L2 read lines.

#define FMA_F32X2(d, a, b, c) \
    asm("fma.rn.f32x2 %0, %1, %2, %3;" : "=l"(d) : "l"(a), "l"(b), "l"(c))
#define MUL_F32X2(d, a, b) \
    asm("mul.rn.f32x2 %0, %1, %2;" : "=l"(d) : "l"(a), "l"(b))
#define CP_ASYNC_8(smem_u32, gptr) \
    asm volatile("cp.async.ca.shared.global [%0], [%1], 8;" :: "r"(smem_u32), "l"(gptr))
#define CP_COMMIT() \
    asm volatile("cp.async.commit_group;" ::: "memory")
#define CP_WAIT_2() \
    asm volatile("cp.async.wait_group 2;" ::: "memory")

namespace la {
constexpr int T = 2048;
constexpr int B = 16;
constexpr int F = 1024;
constexpr int CTX = 20;
constexpr int K = 21;                  // CTX + 1 taps
constexpr int BF2 = (B * F) / 2;       // timestep stride in float2 units = 8192
constexpr int TCHUNK = 64;             // t's per thread
constexpr int STEP = 8;                // t's per inner chunk
constexpr int NCHUNK = TCHUNK / STEP;  // 8, fully unrolled
constexpr int NSTAGE = 3;              // smem ring stages (48 KB static)
constexpr int NTHR = 256;
}  // namespace la

__global__ void __launch_bounds__(256, 2)
lookahead_kernel(const unsigned long long* __restrict__ x2,  // x as float2 (u64 bits)
                 const float* __restrict__ w,
                 unsigned long long* __restrict__ y2)
{
    using namespace la;
    // Ring: [stage][i][tid] — lane-consecutive u64 => conflict-free LDS/STS.
    __shared__ unsigned long long ring[NSTAGE * STEP * NTHR];

    const int tid   = threadIdx.x;
    const int fpair = blockIdx.x * blockDim.x + tid;          // 0..511
    const int b     = blockIdx.y;                             // 0..15
    const int t0    = blockIdx.z * TCHUNK;                    // 0,64,...,1984
    const int f0    = fpair * 2;

    // Pack the two per-feature weight vectors into u64 (lo = f0, hi = f0+1).
    unsigned long long wk[K];
#pragma unroll
    for (int k = 0; k < K; k++) {
        const unsigned int lo = __float_as_uint(__ldg(&w[(size_t)f0 * K + k]));
        const unsigned int hi = __float_as_uint(__ldg(&w[(size_t)(f0 + 1) * K + k]));
        wk[k] = (unsigned long long)lo | ((unsigned long long)hi << 32);
    }

    const unsigned long long* __restrict__ xp = x2 + (size_t)b * (F / 2) + fpair;
    unsigned long long* __restrict__       yp = y2 + (size_t)b * (F / 2) + fpair;

    // This thread's smem base (byte address in shared window for cp.async).
    const unsigned int rbase =
        (unsigned int)__cvta_generic_to_shared(&ring[tid]);

    // Stage s slot i lives at ring[(s*STEP+i)*NTHR + tid].
    auto slot_addr = [&](int s, int i) -> unsigned int {
        return rbase + (unsigned int)((s * STEP + i) * NTHR) * 8u;
    };

    // Prologue: register window head t0..t0+19 via plain LDG (one-time cost).
    unsigned long long win[STEP + CTX];
#pragma unroll
    for (int i = 0; i < CTX; i++)
        win[i] = __ldg(&xp[(size_t)(t0 + i) * BF2]);

    // Prologue: async-issue stages for chunks 0 and 1 (fresh ts t0+20..t0+35).
#pragma unroll
    for (int s = 0; s < 2; s++) {
#pragma unroll
        for (int i = 0; i < STEP; i++) {
            const int t  = t0 + CTX + s * STEP + i;
            const int tl = (t < T) ? t : (T - 1);             // clamp; zeroed on read
            CP_ASYNC_8(slot_addr(s, i), &xp[(size_t)tl * BF2]);
        }
        CP_COMMIT();
    }

#pragma unroll
    for (int c = 0; c < NCHUNK; c++) {
        const int tb = t0 + c * STEP;

        // Issue chunk c+2's stage (or an empty group to keep counts uniform).
        if (c + 2 < NCHUNK) {
            const int s = (c + 2) % NSTAGE;
#pragma unroll
            for (int i = 0; i < STEP; i++) {
                const int t  = t0 + CTX + (c + 2) * STEP + i;
                const int tl = (t < T) ? t : (T - 1);
                CP_ASYNC_8(slot_addr(s, i), &xp[(size_t)tl * BF2]);
            }
        }
        CP_COMMIT();

        // Ensure chunk c's stage has landed (<=2 groups still pending).
        CP_WAIT_2();

        // Pull chunk c's fresh timesteps from smem; zero past the tail.
        {
            const int s = c % NSTAGE;
#pragma unroll
            for (int i = 0; i < STEP; i++) {
                const unsigned long long v = ring[(s * STEP + i) * NTHR + tid];
                win[CTX + i] = (tb + CTX + i < T) ? v : 0ULL;
            }
        }

        // 8 outputs x (1 mul + 20 fma) packed f32x2; streaming stores.
#pragma unroll
        for (int i = 0; i < STEP; i++) {
            unsigned long long acc;
            MUL_F32X2(acc, win[i], wk[0]);
#pragma unroll
            for (int k = 1; k < K; k++)
                FMA_F32X2(acc, win[i + k], wk[k], acc);
            __stcs(&yp[(size_t)(tb + i) * BF2], acc);
        }

        // Rotate carried window — renaming under full unroll.
#pragma unroll
        for (int i = 0; i < CTX; i++)
            win[i] = win[STEP + i];
    }
}

extern "C" void kernel_launch(void* const* d_in, const int* in_sizes, int n_in,
                              void* d_out, int out_size)
{
    using namespace la;
    (void)in_sizes; (void)n_in; (void)out_size;
    const unsigned long long* x2 = (const unsigned long long*)d_in[0];  // x: (T,B,F) f32
    const float*              w  = (const float*)d_in[1];               // weight: (F,21) f32
    // d_in[2] = tail_padding (int, ==1): baked into the zero-fill guard.
    unsigned long long* y2 = (unsigned long long*)d_out;                // y: (T,B,F) f32

    dim3 block(NTHR, 1, 1);
    dim3 grid((F / 2) / NTHR, B, T / TCHUNK);  // (2, 16, 32) = 1024 blocks
    lookahead_kernel<<<grid, block>>>(x2, w, y2);
}